// round 2
// baseline (speedup 1.0000x reference)
#include <cuda_runtime.h>
#include <cstddef>

#define HW   4096
#define Dh   128
#define Cc   256
#define NB   4

// ---------------- scratch (device globals, no allocation) ----------------
__device__ float d_theta[2*NB*HW*Dh];   // [side][b][q][d]
__device__ float d_phi  [2*NB*Dh*HW];   // [side][b][d][k]
__device__ float d_g    [2*NB*HW*Dh];   // [side][b][k][d]
__device__ float d_after[2*NB*HW*Dh];   // [side][b][q][d]
__device__ float d_y    [2*NB*Cc*HW];   // [side][b][c][q]
__device__ float2 d_bn  [2*Cc];         // (mean, invstd)

// ======================= projection kernel (theta/phi/g) =======================
// grid (64 qtiles, B, 6 = side*3+proj), 256 threads, smem 51200B
__global__ __launch_bounds__(256) void proj_kernel(
    const float* __restrict__ left,   const float* __restrict__ right,
    const float* __restrict__ pre_l,  const float* __restrict__ pre_r,
    const float* __restrict__ query_l,const float* __restrict__ key_l,
    const float* __restrict__ query_r,const float* __restrict__ key_r,
    const float* __restrict__ theta_w,const float* __restrict__ theta_b,
    const float* __restrict__ phi_w,  const float* __restrict__ phi_b,
    const float* __restrict__ g_w,    const float* __restrict__ g_b)
{
  extern __shared__ float sm[];
  float* Xs = sm;            // [64 c][68]  (x tile, q contiguous)
  float* Wt = sm + 64*68;    // [64 c][132] (W^T tile, d contiguous)

  const int qt = blockIdx.x, b = blockIdx.y, z = blockIdx.z;
  const int side = z / 3, proj = z - side*3;

  const float* src; const float* w; const float* bias; int cin;
  if (proj == 0)      { src = side ? right : left;  w = theta_w; bias = theta_b; cin = 257; }
  else if (proj == 1) { src = side ? left  : right; w = phi_w;   bias = phi_b;   cin = 256; }
  else                { src = side ? left  : right; w = g_w;     bias = g_b;     cin = 256; }

  const int tid = threadIdx.x, tx = tid & 15, ty = tid >> 4;
  const int q0 = qt * 64;
  const float* xb = src + (size_t)b * Cc * HW;

  float acc[4][8];
  #pragma unroll
  for (int i = 0; i < 4; i++)
    #pragma unroll
    for (int j = 0; j < 8; j++) acc[i][j] = 0.f;

  for (int c0 = 0; c0 < 256; c0 += 64) {
    __syncthreads();
    // X tile: [c][q], q contiguous, float4 loads
    for (int i = tid; i < 64*16; i += 256) {
      int r = i >> 4, c4 = (i & 15) * 4;
      *(float4*)&Xs[r*68 + c4] = *(const float4*)&xb[(size_t)(c0 + r)*HW + q0 + c4];
    }
    // W^T tile: read w[d][c] coalesced, store transposed [c][d]
    for (int i = tid; i < 128*64; i += 256) {
      int d = i >> 6, c = i & 63;
      Wt[c*132 + d] = w[d*cin + c0 + c];
    }
    __syncthreads();
    #pragma unroll 4
    for (int c = 0; c < 64; c++) {
      float4 q4 = *(const float4*)&Xs[c*68 + ty*4];
      float4 w0 = *(const float4*)&Wt[c*132 + tx*8];
      float4 w1 = *(const float4*)&Wt[c*132 + tx*8 + 4];
      float qv[4] = {q4.x, q4.y, q4.z, q4.w};
      float wv[8] = {w0.x,w0.y,w0.z,w0.w, w1.x,w1.y,w1.z,w1.w};
      #pragma unroll
      for (int qq = 0; qq < 4; qq++)
        #pragma unroll
        for (int dd = 0; dd < 8; dd++)
          acc[qq][dd] += qv[qq]*wv[dd];
    }
  }

  const int d0 = tx*8;
  const int sb = side*NB + b;
  float outv[4][8];

  if (proj == 0) {
    const float* pre = side ? pre_r : pre_l;
    const float* qry = side ? query_r : query_l;
    float prev[4];
    #pragma unroll
    for (int qq = 0; qq < 4; qq++)
      prev[qq] = pre[(size_t)b*HW + q0 + ty*4 + qq] * (1.0f/128.0f);
    #pragma unroll
    for (int qq = 0; qq < 4; qq++) {
      int q = q0 + ty*4 + qq;
      #pragma unroll
      for (int dd = 0; dd < 8; dd++) {
        int d = d0 + dd;
        outv[qq][dd] = acc[qq][dd] + bias[d] + w[d*257 + 256]*prev[qq]
                     + qry[((size_t)b*Dh + d)*HW + q];
      }
    }
    float* dst = d_theta + (size_t)sb*HW*Dh;
    #pragma unroll
    for (int qq = 0; qq < 4; qq++) {
      size_t o = (size_t)(q0 + ty*4 + qq)*Dh + d0;
      *(float4*)&dst[o]     = make_float4(outv[qq][0],outv[qq][1],outv[qq][2],outv[qq][3]);
      *(float4*)&dst[o + 4] = make_float4(outv[qq][4],outv[qq][5],outv[qq][6],outv[qq][7]);
    }
  } else if (proj == 1) {
    const float* kf = side ? key_l : key_r;
    #pragma unroll
    for (int qq = 0; qq < 4; qq++) {
      int q = q0 + ty*4 + qq;
      #pragma unroll
      for (int dd = 0; dd < 8; dd++) {
        int d = d0 + dd;
        outv[qq][dd] = acc[qq][dd] + bias[d] + kf[((size_t)b*Dh + d)*HW + q];
      }
    }
    float* dst = d_phi + (size_t)sb*Dh*HW;
    #pragma unroll
    for (int dd = 0; dd < 8; dd++) {
      *(float4*)&dst[(size_t)(d0+dd)*HW + q0 + ty*4] =
        make_float4(outv[0][dd],outv[1][dd],outv[2][dd],outv[3][dd]);
    }
  } else {
    #pragma unroll
    for (int qq = 0; qq < 4; qq++)
      #pragma unroll
      for (int dd = 0; dd < 8; dd++)
        outv[qq][dd] = acc[qq][dd] + bias[d0+dd];
    float* dst = d_g + (size_t)sb*HW*Dh;
    #pragma unroll
    for (int qq = 0; qq < 4; qq++) {
      size_t o = (size_t)(q0 + ty*4 + qq)*Dh + d0;
      *(float4*)&dst[o]     = make_float4(outv[qq][0],outv[qq][1],outv[qq][2],outv[qq][3]);
      *(float4*)&dst[o + 4] = make_float4(outv[qq][4],outv[qq][5],outv[qq][6],outv[qq][7]);
    }
  }
}

// ======================= fused flash attention + soft-argmax =======================
// grid (64 qtiles, B, 2 sides), 256 threads, smem 119808B
__global__ __launch_bounds__(256) void flash_kernel(float* __restrict__ out)
{
  extern __shared__ float sm[];
  float* Qs = sm;                 // [64][132]
  float* Ks = Qs + 64*132;        // [128][68]  ([d][k])
  float* Gs = Ks + 128*68;        // [64][132]  ([k][d])
  float* Ps = Gs + 64*132;        // [64][68]

  const int qt = blockIdx.x, b = blockIdx.y, side = blockIdx.z;
  const int sb = side*NB + b;
  const float* Qg = d_theta + (size_t)sb*HW*Dh;
  const float* Kg = d_phi   + (size_t)sb*Dh*HW;
  const float* Gg = d_g     + (size_t)sb*HW*Dh;
  float*       Og = d_after + (size_t)sb*HW*Dh;

  const int tid = threadIdx.x, tx = tid & 15, ty = tid >> 4;
  const int q0 = qt * 64;

  for (int i = tid; i < 64*32; i += 256) {
    int r = i >> 5, c4 = (i & 31) * 4;
    *(float4*)&Qs[r*132 + c4] = *(const float4*)&Qg[(size_t)(q0+r)*Dh + c4];
  }

  float m[4], lp[4], cp[4], o[4][8];
  #pragma unroll
  for (int qq = 0; qq < 4; qq++) {
    m[qq] = -1e30f; lp[qq] = 0.f; cp[qq] = 0.f;
    #pragma unroll
    for (int dd = 0; dd < 8; dd++) o[qq][dd] = 0.f;
  }

  for (int kt = 0; kt < 64; kt++) {
    const int k0 = kt * 64;
    __syncthreads();
    for (int i = tid; i < 128*16; i += 256) {
      int r = i >> 4, c4 = (i & 15) * 4;
      *(float4*)&Ks[r*68 + c4] = *(const float4*)&Kg[(size_t)r*HW + k0 + c4];
    }
    for (int i = tid; i < 64*32; i += 256) {
      int r = i >> 5, c4 = (i & 31) * 4;
      *(float4*)&Gs[r*132 + c4] = *(const float4*)&Gg[(size_t)(k0+r)*Dh + c4];
    }
    __syncthreads();

    // ---- S = Q K  (64x64 tile, each thread 4q x 4k) ----
    float s[4][4];
    #pragma unroll
    for (int qq = 0; qq < 4; qq++)
      #pragma unroll
      for (int kk = 0; kk < 4; kk++) s[qq][kk] = 0.f;

    #pragma unroll 2
    for (int d4 = 0; d4 < 32; d4++) {
      float kv[4][4];
      #pragma unroll
      for (int j = 0; j < 4; j++) {
        float4 t = *(const float4*)&Ks[(d4*4+j)*68 + tx*4];
        kv[j][0]=t.x; kv[j][1]=t.y; kv[j][2]=t.z; kv[j][3]=t.w;
      }
      #pragma unroll
      for (int qq = 0; qq < 4; qq++) {
        float4 t = *(const float4*)&Qs[(ty*4+qq)*132 + d4*4];
        float qv[4] = {t.x, t.y, t.z, t.w};
        #pragma unroll
        for (int j = 0; j < 4; j++)
          #pragma unroll
          for (int kk = 0; kk < 4; kk++)
            s[qq][kk] += qv[j]*kv[j][kk];
      }
    }

    // ---- online softmax update ----
    float tmax[4];
    #pragma unroll
    for (int qq = 0; qq < 4; qq++)
      tmax[qq] = fmaxf(fmaxf(s[qq][0],s[qq][1]), fmaxf(s[qq][2],s[qq][3]));
    #pragma unroll
    for (int off = 8; off; off >>= 1)
      #pragma unroll
      for (int qq = 0; qq < 4; qq++)
        tmax[qq] = fmaxf(tmax[qq], __shfl_xor_sync(0xffffffffu, tmax[qq], off));

    #pragma unroll
    for (int qq = 0; qq < 4; qq++) {
      float mn  = fmaxf(m[qq], tmax[qq]);
      float scl = __expf(m[qq] - mn);
      m[qq] = mn;
      float rs = 0.f, rc = 0.f;
      #pragma unroll
      for (int kk = 0; kk < 4; kk++) {
        float p = __expf(s[qq][kk] - mn);
        s[qq][kk] = p;
        rs += p;
        rc += p * (float)((k0 + tx*4 + kk) & 127);
      }
      lp[qq] = lp[qq]*scl + rs;
      cp[qq] = cp[qq]*scl + rc;
      #pragma unroll
      for (int dd = 0; dd < 8; dd++) o[qq][dd] *= scl;
    }

    #pragma unroll
    for (int qq = 0; qq < 4; qq++)
      *(float4*)&Ps[(ty*4+qq)*68 + tx*4] =
        make_float4(s[qq][0], s[qq][1], s[qq][2], s[qq][3]);
    __syncthreads();

    // ---- O += P G  (each thread 4q x 8d) ----
    #pragma unroll 2
    for (int k4 = 0; k4 < 16; k4++) {
      float gv[4][8];
      #pragma unroll
      for (int j = 0; j < 4; j++) {
        float4 a = *(const float4*)&Gs[(k4*4+j)*132 + tx*8];
        float4 c = *(const float4*)&Gs[(k4*4+j)*132 + tx*8 + 4];
        gv[j][0]=a.x; gv[j][1]=a.y; gv[j][2]=a.z; gv[j][3]=a.w;
        gv[j][4]=c.x; gv[j][5]=c.y; gv[j][6]=c.z; gv[j][7]=c.w;
      }
      #pragma unroll
      for (int qq = 0; qq < 4; qq++) {
        float4 t = *(const float4*)&Ps[(ty*4+qq)*68 + k4*4];
        float pv[4] = {t.x, t.y, t.z, t.w};
        #pragma unroll
        for (int j = 0; j < 4; j++)
          #pragma unroll
          for (int dd = 0; dd < 8; dd++)
            o[qq][dd] += pv[j]*gv[j][dd];
      }
    }
  }

  // reduce l and c across the 16 tx lanes
  #pragma unroll
  for (int off = 8; off; off >>= 1)
    #pragma unroll
    for (int qq = 0; qq < 4; qq++) {
      lp[qq] += __shfl_xor_sync(0xffffffffu, lp[qq], off);
      cp[qq] += __shfl_xor_sync(0xffffffffu, cp[qq], off);
    }

  const size_t IDX_BASE = (size_t)2*NB*Cc*HW;
  #pragma unroll
  for (int qq = 0; qq < 4; qq++) {
    float inv = 1.0f / lp[qq];
    int q = q0 + ty*4 + qq;
    size_t oo = (size_t)q*Dh + tx*8;
    *(float4*)&Og[oo]     = make_float4(o[qq][0]*inv, o[qq][1]*inv, o[qq][2]*inv, o[qq][3]*inv);
    *(float4*)&Og[oo + 4] = make_float4(o[qq][4]*inv, o[qq][5]*inv, o[qq][6]*inv, o[qq][7]*inv);
    if (tx == 0) {
      out[IDX_BASE + (size_t)side*NB*HW + (size_t)b*HW + q] =
        (float)(q & 127) - cp[qq]*inv;
    }
  }
}

// ======================= up-projection =======================
// grid (64 qtiles, B, 4 = side*2 + chalf), 256 threads, smem 101376B
__global__ __launch_bounds__(256) void up_kernel(
    const float* __restrict__ up_w, const float* __restrict__ up_b)
{
  extern __shared__ float sm[];
  float* As = sm;            // [64 q][132]
  float* Ws = sm + 64*132;   // [128 d][132]  ([d][c] transposed)

  const int qt = blockIdx.x, b = blockIdx.y, z = blockIdx.z;
  const int side = z >> 1, ch = z & 1;
  const int sb = side*NB + b;
  const float* Ap = d_after + (size_t)sb*HW*Dh;
  float*       Yp = d_y     + (size_t)sb*Cc*HW;
  const int c0 = ch*128;
  const int tid = threadIdx.x, tx = tid & 15, ty = tid >> 4;
  const int q0 = qt*64;

  for (int i = tid; i < 64*32; i += 256) {
    int r = i >> 5, c4 = (i & 31) * 4;
    *(float4*)&As[r*132 + c4] = *(const float4*)&Ap[(size_t)(q0+r)*Dh + c4];
  }
  for (int i = tid; i < 128*32; i += 256) {
    int c = i >> 5, d4 = (i & 31) * 4;
    float4 v = *(const float4*)&up_w[(size_t)(c0+c)*Dh + d4];
    Ws[(d4+0)*132 + c] = v.x;
    Ws[(d4+1)*132 + c] = v.y;
    Ws[(d4+2)*132 + c] = v.z;
    Ws[(d4+3)*132 + c] = v.w;
  }
  __syncthreads();

  float acc[4][8];
  #pragma unroll
  for (int i = 0; i < 4; i++)
    #pragma unroll
    for (int j = 0; j < 8; j++) acc[i][j] = 0.f;

  #pragma unroll 2
  for (int d4 = 0; d4 < 32; d4++) {
    float wv[4][8];
    #pragma unroll
    for (int j = 0; j < 4; j++) {
      float4 a = *(const float4*)&Ws[(d4*4+j)*132 + tx*8];
      float4 c = *(const float4*)&Ws[(d4*4+j)*132 + tx*8 + 4];
      wv[j][0]=a.x; wv[j][1]=a.y; wv[j][2]=a.z; wv[j][3]=a.w;
      wv[j][4]=c.x; wv[j][5]=c.y; wv[j][6]=c.z; wv[j][7]=c.w;
    }
    #pragma unroll
    for (int qq = 0; qq < 4; qq++) {
      float4 t = *(const float4*)&As[(ty*4+qq)*132 + d4*4];
      float av[4] = {t.x, t.y, t.z, t.w};
      #pragma unroll
      for (int j = 0; j < 4; j++)
        #pragma unroll
        for (int cc = 0; cc < 8; cc++)
          acc[qq][cc] += av[j]*wv[j][cc];
    }
  }

  #pragma unroll
  for (int cc = 0; cc < 8; cc++) {
    int c = c0 + tx*8 + cc;
    float bb = up_b[c];
    *(float4*)&Yp[(size_t)c*HW + q0 + ty*4] =
      make_float4(acc[0][cc]+bb, acc[1][cc]+bb, acc[2][cc]+bb, acc[3][cc]+bb);
  }
}

// ======================= BN stats (per side, per channel) =======================
__global__ __launch_bounds__(256) void bn_stats_kernel()
{
  const int c = blockIdx.x, side = blockIdx.y;
  float s = 0.f, s2 = 0.f;
  for (int b = 0; b < NB; b++) {
    const float* p = d_y + (size_t)((side*NB + b)*Cc + c)*HW;
    for (int i = threadIdx.x; i < HW; i += 256) {
      float v = p[i];
      s += v; s2 += v*v;
    }
  }
  __shared__ float red[64];
  #pragma unroll
  for (int off = 16; off; off >>= 1) {
    s  += __shfl_down_sync(0xffffffffu, s,  off);
    s2 += __shfl_down_sync(0xffffffffu, s2, off);
  }
  int w = threadIdx.x >> 5;
  if ((threadIdx.x & 31) == 0) { red[w] = s; red[w + 32] = s2; }
  __syncthreads();
  if (threadIdx.x == 0) {
    float ts = 0.f, ts2 = 0.f;
    #pragma unroll
    for (int i = 0; i < 8; i++) { ts += red[i]; ts2 += red[i + 32]; }
    float mean = ts * (1.0f/16384.0f);
    float var  = ts2 * (1.0f/16384.0f) - mean*mean;
    d_bn[side*Cc + c] = make_float2(mean, rsqrtf(var + 1e-5f));
  }
}

// ======================= final: residual + BN apply =======================
__global__ __launch_bounds__(256) void final_kernel(
    const float* __restrict__ left, const float* __restrict__ right,
    const float* __restrict__ gamma, const float* __restrict__ beta,
    float* __restrict__ out)
{
  size_t i = ((size_t)blockIdx.x*256 + threadIdx.x) * 4;
  int q = (int)(i & 4095);
  size_t t = i >> 12;
  int c = (int)(t & 255); t >>= 8;
  int b = (int)(t & 3);
  int side = (int)(t >> 2);
  const float* x = side ? right : left;
  float4 xv = *(const float4*)&x[(((size_t)b*Cc + c) << 12) + q];
  float4 yv = *(const float4*)&d_y[i];
  float2 st = d_bn[side*Cc + c];
  float ga = gamma[c]*st.y;
  float be = beta[c] - ga*st.x;
  float4 r;
  r.x = xv.x + yv.x*ga + be;
  r.y = xv.y + yv.y*ga + be;
  r.z = xv.z + yv.z*ga + be;
  r.w = xv.w + yv.w*ga + be;
  *(float4*)&out[i] = r;
}

// ======================= launch =======================
extern "C" void kernel_launch(void* const* d_in, const int* in_sizes, int n_in,
                              void* d_out, int out_size)
{
  const float* left    = (const float*)d_in[0];
  const float* right   = (const float*)d_in[1];
  const float* pre_l   = (const float*)d_in[2];
  const float* pre_r   = (const float*)d_in[3];
  const float* query_l = (const float*)d_in[4];
  const float* key_l   = (const float*)d_in[5];
  const float* query_r = (const float*)d_in[6];
  const float* key_r   = (const float*)d_in[7];
  const float* theta_w = (const float*)d_in[8];
  const float* theta_b = (const float*)d_in[9];
  const float* phi_w   = (const float*)d_in[10];
  const float* phi_b   = (const float*)d_in[11];
  const float* g_w     = (const float*)d_in[12];
  const float* g_b     = (const float*)d_in[13];
  const float* up_w    = (const float*)d_in[14];
  const float* up_b    = (const float*)d_in[15];
  const float* bn_g    = (const float*)d_in[16];
  const float* bn_b    = (const float*)d_in[17];
  float* out = (float*)d_out;

  const int PROJ_SMEM  = (64*68 + 64*132) * 4;            // 51200
  const int FLASH_SMEM = (64*132 + 128*68 + 64*132 + 64*68) * 4; // 119808
  const int UP_SMEM    = (64*132 + 128*132) * 4;          // 101376
  cudaFuncSetAttribute(proj_kernel,  cudaFuncAttributeMaxDynamicSharedMemorySize, PROJ_SMEM);
  cudaFuncSetAttribute(flash_kernel, cudaFuncAttributeMaxDynamicSharedMemorySize, FLASH_SMEM);
  cudaFuncSetAttribute(up_kernel,    cudaFuncAttributeMaxDynamicSharedMemorySize, UP_SMEM);

  proj_kernel<<<dim3(64, NB, 6), 256, PROJ_SMEM>>>(
      left, right, pre_l, pre_r, query_l, key_l, query_r, key_r,
      theta_w, theta_b, phi_w, phi_b, g_w, g_b);

  flash_kernel<<<dim3(64, NB, 2), 256, FLASH_SMEM>>>(out);

  up_kernel<<<dim3(64, NB, 4), 256, UP_SMEM>>>(up_w, up_b);

  bn_stats_kernel<<<dim3(Cc, 2), 256>>>();

  final_kernel<<<dim3(2*NB*Cc*HW/4/256), 256>>>(left, right, bn_g, bn_b, out);
}